// round 7
// baseline (speedup 1.0000x reference)
#include <cuda_runtime.h>

// StealNMSLoss — single fused kernel, branchless bins, last-block reduction.
// Interior blocks: double-Sobel composed into separable 5x5 (one smem stage).
// Border blocks: exact nested-clamp two-stage path.
// Inputs: d_in[0]=true_labels (4,19,512,512) f32, d_in[1]=pred_labels f32.
// Output: scalar f32 = -(1/B) * sum over (C,H,W) of term.
//
// Composed 5x5 kernels (cross-correlation, /64 folded into thresholds):
//   gxx: col (1,4,6,4,1)   x row (1,0,-2,0,1)
//   gxy: col (-1,-2,0,2,1) x row (-1,-2,0,2,1)
//   gyy: col (1,0,-2,0,1)  x row (1,4,6,4,1)
// Bin classification (z = gyy*sign(eps-gxy)/(gxx+eps), arctan monotone):
//   horizontal  : |z| <  tan22.5            taps +-(0,1)
//   counter-diag: z in [tan22.5, tan67.5)   taps +-(1,-1)
//   vertical    : z >= tan67.5 or z < -tan67.5   taps +-(1,0)
//   leading-diag: z in (-tan67.5, -tan22.5) taps +-(1,1)
//   z == -tan67.5 exactly, or 0/0 (NaN) -> no bin

#define HH 512
#define WW 512
#define NIMG 76
#define NBX (WW / 32)
#define NBY (HH / 32)
#define NBLK (NBX * NBY * NIMG)
#define EPSC 1e-7f
#define EPS64 6.4e-6f   // 64 * EPSC

__device__ float g_part[NBLK];
__device__ unsigned int g_cnt;   // zero-init; atomicInc wraps -> deterministic

__launch_bounds__(256)
__global__ void nms_main_kernel(const float* __restrict__ tl,
                                const float* __restrict__ pl,
                                float* __restrict__ out) {
    __shared__ float st[36][37];   // t tile, halo 2 (clamped at border)
    __shared__ float se[34][35];   // exp(0.1*p), halo 1 (reflected)
    __shared__ union {
        float h[3][36][33];        // interior: hxx/hxy/hyy row factors
        float g[2][34][35];        // border: sgx/sgy (first-stage Sobel)
    } sb;

    const int x0 = blockIdx.x * 32;
    const int y0 = blockIdx.y * 32;
    const size_t base = (size_t)blockIdx.z * (HH * WW);
    const float* t = tl + base;
    const float* p = pl + base;
    const int tid = threadIdx.y * 32 + threadIdx.x;
    const int tx = threadIdx.x;
    const int ty0 = threadIdx.y * 4;

    const bool border = (blockIdx.x == 0) | (blockIdx.x == NBX - 1) |
                        (blockIdx.y == 0) | (blockIdx.y == NBY - 1);

    float acc = 0.0f;

    if (!border) {
        // ================= interior fast path =================
        const float* tb = t + (size_t)(y0 - 2) * WW + (x0 - 2);
        for (int i = tid; i < 36 * 36; i += 256) {
            int iy = i / 36, ix = i - iy * 36;
            st[iy][ix] = __ldg(tb + (size_t)iy * WW + ix);
        }
        const float* pb = p + (size_t)(y0 - 1) * WW + (x0 - 1);
        for (int i = tid; i < 34 * 34; i += 256) {
            int iy = i / 34, ix = i - iy * 34;
            se[iy][ix] = __expf(0.1f * __ldg(pb + (size_t)iy * WW + ix));
        }
        __syncthreads();

        // horizontal 5-tap factors (5 shared reads feed 3 outputs)
        for (int i = tid; i < 36 * 32; i += 256) {
            int r = i >> 5, c = i & 31;
            float s0 = st[r][c],     s1 = st[r][c + 1], s2 = st[r][c + 2];
            float s3 = st[r][c + 3], s4 = st[r][c + 4];
            sb.h[0][r][c] = (s0 + s4) - 2.0f * s2;                    // hxx
            sb.h[1][r][c] = 2.0f * (s3 - s1) + (s4 - s0);             // hxy
            sb.h[2][r][c] = (s0 + s4) + 4.0f * (s1 + s3) + 6.0f * s2; // hyy
        }
        __syncthreads();

        // vertical rolling combine: 4 consecutive rows per thread
        float A0, A1, A2, A3, A4;   // hxx window
        float B0, B1, B2, B3, B4;   // hxy window
        float C0, C1, C2, C3, C4;   // hyy window
        A0 = sb.h[0][ty0][tx];     B0 = sb.h[1][ty0][tx];     C0 = sb.h[2][ty0][tx];
        A1 = sb.h[0][ty0 + 1][tx]; B1 = sb.h[1][ty0 + 1][tx]; C1 = sb.h[2][ty0 + 1][tx];
        A2 = sb.h[0][ty0 + 2][tx]; B2 = sb.h[1][ty0 + 2][tx]; C2 = sb.h[2][ty0 + 2][tx];
        A3 = sb.h[0][ty0 + 3][tx]; B3 = sb.h[1][ty0 + 3][tx]; C3 = sb.h[2][ty0 + 3][tx];
#pragma unroll
        for (int i = 0; i < 4; i++) {
            const int r = ty0 + i + 4;
            A4 = sb.h[0][r][tx]; B4 = sb.h[1][r][tx]; C4 = sb.h[2][r][tx];
            const int py = ty0 + i;
            float tc = st[py + 2][tx + 2];
            if (tc > 0.0f) {
                // 64x-scaled second derivatives
                float gxx = (A0 + A4) + 4.0f * (A1 + A3) + 6.0f * A2;
                float gxy = (B4 - B0) + 2.0f * (B3 - B1);
                float gyy = (C0 + C4) - 2.0f * C2;

                float sv = EPS64 - gxy;
                float s = (sv > 0.0f) ? 1.0f : ((sv < 0.0f) ? -1.0f : 0.0f);
                float nmr = gyy * s;
                float den = gxx + EPS64;
                float nn = (den < 0.0f) ? -nmr : nmr;
                float dd = fabsf(den);
                float th1 = 0.41421356237309503f * dd;
                float th2 = 2.41421356237309510f * dd;

                bool vert = (nn >= th2) | (nn < -th2);
                bool cd   = !vert & (nn >= th1);
                bool hz   = !vert & !cd & (nn >= -th1);
                bool ld   = !vert & !cd & !hz & (nn > -th2);
                bool valid = (vert | cd | hz | ld) & !((nn == 0.0f) & (dd == 0.0f));

                if (valid) {
                    int dy = hz ? 0 : 1;
                    int dx = vert ? 0 : (cd ? -1 : 1);
                    int cyy = py + 1, cxx = tx + 1;
                    float ec = se[cyy][cxx];
                    float f = se[cyy - dy][cxx - dx] + ec + se[cyy + dy][cxx + dx];
                    float rto = __fdividef(ec, f + EPSC);
                    rto = fminf(fmaxf(rto, EPSC), 1.0f);
                    acc += __logf(rto);
                }
            }
            A0 = A1; A1 = A2; A2 = A3; A3 = A4;
            B0 = B1; B1 = B2; B2 = B3; B3 = B4;
            C0 = C1; C1 = C2; C2 = C3; C3 = C4;
        }
    } else {
        // ================= border path (exact nested clamp) =================
        for (int i = tid; i < 36 * 36; i += 256) {
            int iy = i / 36, ix = i - iy * 36;
            int gy = y0 - 2 + iy; gy = gy < 0 ? 0 : (gy > HH - 1 ? HH - 1 : gy);
            int gx = x0 - 2 + ix; gx = gx < 0 ? 0 : (gx > WW - 1 ? WW - 1 : gx);
            st[iy][ix] = __ldg(t + (size_t)gy * WW + gx);
        }
        for (int i = tid; i < 34 * 34; i += 256) {
            int iy = i / 34, ix = i - iy * 34;
            int gy = y0 - 1 + iy; gy = gy < 0 ? -gy : (gy >= HH ? 2 * HH - 2 - gy : gy);
            int gx = x0 - 1 + ix; gx = gx < 0 ? -gx : (gx >= WW ? 2 * WW - 2 - gx : gx);
            se[iy][ix] = __expf(0.1f * __ldg(p + (size_t)gy * WW + gx));
        }
        __syncthreads();
        // stage 1: first Sobel at CLAMPED global coords (nested replicate pad)
        for (int i = tid; i < 34 * 34; i += 256) {
            int iy = i / 34, ix = i - iy * 34;
            int cy = y0 - 1 + iy; cy = cy < 0 ? 0 : (cy > HH - 1 ? HH - 1 : cy);
            int cx = x0 - 1 + ix; cx = cx < 0 ? 0 : (cx > WW - 1 ? WW - 1 : cx);
            int ay = cy - y0 + 2;
            int ax = cx - x0 + 2;
            float A = st[ay - 1][ax - 1], B = st[ay - 1][ax], C = st[ay - 1][ax + 1];
            float D = st[ay][ax - 1],                          E = st[ay][ax + 1];
            float F = st[ay + 1][ax - 1], G = st[ay + 1][ax], Hv = st[ay + 1][ax + 1];
            sb.g[0][iy][ix] = 0.125f * ((C - A) + 2.0f * (E - D) + (Hv - F));
            sb.g[1][iy][ix] = 0.125f * ((F - A) + 2.0f * (G - B) + (Hv - C));
        }
        __syncthreads();

        // stage 2: rolling 3-row window over sgx/sgy
        float X0, X1, X2, Y0, Y1, Y2, W0, W1, W2;
        {
            float a = sb.g[0][ty0][tx], b = sb.g[0][ty0][tx + 2];
            float c = sb.g[1][ty0][tx], d = sb.g[1][ty0][tx + 1], e = sb.g[1][ty0][tx + 2];
            X0 = b - a; Y0 = e - c; W0 = c + 2.0f * d + e;
            a = sb.g[0][ty0 + 1][tx]; b = sb.g[0][ty0 + 1][tx + 2];
            c = sb.g[1][ty0 + 1][tx]; d = sb.g[1][ty0 + 1][tx + 1]; e = sb.g[1][ty0 + 1][tx + 2];
            X1 = b - a; Y1 = e - c; W1 = c + 2.0f * d + e;
        }
#pragma unroll
        for (int i = 0; i < 4; i++) {
            const int r = ty0 + i + 2;
            {
                float a = sb.g[0][r][tx], b = sb.g[0][r][tx + 2];
                float c = sb.g[1][r][tx], d = sb.g[1][r][tx + 1], e = sb.g[1][r][tx + 2];
                X2 = b - a; Y2 = e - c; W2 = c + 2.0f * d + e;
            }
            const int py = ty0 + i;
            float tc = st[py + 2][tx + 2];
            if (tc > 0.0f) {
                float gxx = 0.125f * (X0 + 2.0f * X1 + X2);
                float gxy = 0.125f * (Y0 + 2.0f * Y1 + Y2);
                float gyy = 0.125f * (W2 - W0);

                float sv = EPSC - gxy;
                float s = (sv > 0.0f) ? 1.0f : ((sv < 0.0f) ? -1.0f : 0.0f);
                float nmr = gyy * s;
                float den = gxx + EPSC;
                float nn = (den < 0.0f) ? -nmr : nmr;
                float dd = fabsf(den);
                float th1 = 0.41421356237309503f * dd;
                float th2 = 2.41421356237309510f * dd;

                bool vert = (nn >= th2) | (nn < -th2);
                bool cd   = !vert & (nn >= th1);
                bool hz   = !vert & !cd & (nn >= -th1);
                bool ld   = !vert & !cd & !hz & (nn > -th2);
                bool valid = (vert | cd | hz | ld) & !((nn == 0.0f) & (dd == 0.0f));

                if (valid) {
                    int dy = hz ? 0 : 1;
                    int dx = vert ? 0 : (cd ? -1 : 1);
                    int cyy = py + 1, cxx = tx + 1;
                    float ec = se[cyy][cxx];
                    float f = se[cyy - dy][cxx - dx] + ec + se[cyy + dy][cxx + dx];
                    float rto = __fdividef(ec, f + EPSC);
                    rto = fminf(fmaxf(rto, EPSC), 1.0f);
                    acc += __logf(rto);
                }
            }
            X0 = X1; X1 = X2; Y0 = Y1; Y1 = Y2; W0 = W1; W1 = W2;
        }
    }

    // ---- block reduce (float) -> partial slot ----
#pragma unroll
    for (int off = 16; off > 0; off >>= 1)
        acc += __shfl_down_sync(0xffffffffu, acc, off);
    __shared__ float wsum[8];
    if ((tid & 31) == 0) wsum[tid >> 5] = acc;
    __syncthreads();
    const int bid = blockIdx.x + NBX * (blockIdx.y + NBY * blockIdx.z);
    if (tid == 0) {
        g_part[bid] = wsum[0] + wsum[1] + wsum[2] + wsum[3]
                    + wsum[4] + wsum[5] + wsum[6] + wsum[7];
    }

    // ---- last block performs the final reduction ----
    __threadfence();
    __shared__ bool is_last;
    if (tid == 0) {
        unsigned int v = atomicInc(&g_cnt, NBLK - 1);  // wraps -> deterministic
        is_last = (v == NBLK - 1);
    }
    __syncthreads();
    if (is_last) {
        double s = 0.0;
        for (int i = tid; i < NBLK; i += 256) s += (double)__ldcg(&g_part[i]);
#pragma unroll
        for (int off = 16; off > 0; off >>= 1)
            s += __shfl_down_sync(0xffffffffu, s, off);
        __shared__ double dsum[8];
        if ((tid & 31) == 0) dsum[tid >> 5] = s;
        __syncthreads();
        if (tid == 0) {
            double tot = dsum[0] + dsum[1] + dsum[2] + dsum[3]
                       + dsum[4] + dsum[5] + dsum[6] + dsum[7];
            out[0] = (float)(-tot * 0.25);   // mean over B=4, negate
        }
    }
}

extern "C" void kernel_launch(void* const* d_in, const int* in_sizes, int n_in,
                              void* d_out, int out_size) {
    const float* tl = (const float*)d_in[0];
    const float* pl = (const float*)d_in[1];
    float* out = (float*)d_out;

    dim3 grid(NBX, NBY, NIMG);
    dim3 block(32, 8);
    nms_main_kernel<<<grid, block>>>(tl, pl, out);
}